// round 6
// baseline (speedup 1.0000x reference)
#include <cuda_runtime.h>
#include <math.h>

#define D_FEAT 128
#define FULL 0xffffffffu
#define MAX_NODES 100000

// Scratch: per-node L2 norms of feature rows (allocation-free __device__ global).
__device__ float g_norms[MAX_NODES];

// ---------------------------------------------------------------------------
// Kernel 1: precompute ||features[n]|| for all nodes. Warp per node.
// ---------------------------------------------------------------------------
__global__ void __launch_bounds__(256) norms_kernel(const float* __restrict__ feats,
                                                    int n_nodes) {
    int warp = (blockIdx.x * blockDim.x + threadIdx.x) >> 5;
    int lane = threadIdx.x & 31;
    if (warp >= n_nodes) return;
    const float4* row = (const float4*)(feats + (size_t)warp * D_FEAT);
    float4 v = row[lane];
    float s = v.x * v.x + v.y * v.y + v.z * v.z + v.w * v.w;
#pragma unroll
    for (int o = 16; o; o >>= 1) s += __shfl_xor_sync(FULL, s, o);
    if (lane == 0) g_norms[warp] = sqrtf(s);
}

// ---------------------------------------------------------------------------
// Kernel 2: per-node cosine top-k aggregation. Warp per batch node.
//   lane l holds float4 center[4l:4l+4]; each neighbor row load is one
//   coalesced LDG.128 across the warp (512B contiguous).
// ---------------------------------------------------------------------------
__device__ __forceinline__ unsigned f2ord(float f) {
    unsigned u = __float_as_uint(f);
    return (u & 0x80000000u) ? ~u : (u | 0x80000000u);
}

__global__ void __launch_bounds__(256) agg_kernel(const float* __restrict__ feats,
                                                  const int* __restrict__ nodes,
                                                  const int* __restrict__ neighs,
                                                  const int* __restrict__ ns_ptr,
                                                  float* __restrict__ out,
                                                  int B, int K) {
    int warp = (blockIdx.x * blockDim.x + threadIdx.x) >> 5;
    int lane = threadIdx.x & 31;
    if (warp >= B) return;

    int ns = ns_ptr ? __ldg(ns_ptr) : 10;
    if (ns > K) ns = K;

    int node = __ldg(&nodes[warp]);                       // uniform broadcast
    int myneigh = (lane < K) ? __ldg(&neighs[(size_t)warp * K + lane]) : 0;
    float mynorm = g_norms[myneigh];                      // lane k's neighbor norm
    float cnorm = g_norms[node];

    const float4* crow = (const float4*)(feats + (size_t)node * D_FEAT);
    float4 c = crow[lane];

    // --- cosine similarity of center vs each neighbor; sim lands on lane k ---
    float mydot = 0.0f;
    if (K == 32) {
#pragma unroll
        for (int k = 0; k < 32; k++) {
            int idx = __shfl_sync(FULL, myneigh, k);
            const float4* row = (const float4*)(feats + (size_t)idx * D_FEAT);
            float4 v = row[lane];
            float p = v.x * c.x + v.y * c.y + v.z * c.z + v.w * c.w;
#pragma unroll
            for (int o = 16; o; o >>= 1) p += __shfl_xor_sync(FULL, p, o);
            if (lane == k) mydot = p;
        }
    } else {
        for (int k = 0; k < K; k++) {
            int idx = __shfl_sync(FULL, myneigh, k);
            const float4* row = (const float4*)(feats + (size_t)idx * D_FEAT);
            float4 v = row[lane];
            float p = v.x * c.x + v.y * c.y + v.z * c.z + v.w * c.w;
#pragma unroll
            for (int o = 16; o; o >>= 1) p += __shfl_xor_sync(FULL, p, o);
            if (lane == k) mydot = p;
        }
    }

    float sim = mydot / (cnorm * mynorm);

    // --- top-ns selection: redux.max on order-transformed key, exact
    //     lowest-index tie-break via ballot+ffs ---
    unsigned key = f2ord(sim);
    if (lane >= K) key = 0u;                              // invalid lanes never win
    unsigned sel = 0u;                                    // same value on all lanes
    for (int i = 0; i < ns; i++) {
        unsigned m = __reduce_max_sync(FULL, key);
        unsigned b = __ballot_sync(FULL, key == m);
        int kk = __ffs(b) - 1;                            // lowest index on ties
        sel |= 1u << kk;
        if (lane == kk) key = 0u;                         // knock out winner
    }

    // --- mean of selected rows (re-gather: rows are L1-hot) + relu ---
    float4 acc = make_float4(0.f, 0.f, 0.f, 0.f);
    unsigned m2 = sel;
    while (m2) {
        int k = __ffs(m2) - 1;
        m2 &= m2 - 1;
        int idx = __shfl_sync(FULL, myneigh, k);
        const float4* row = (const float4*)(feats + (size_t)idx * D_FEAT);
        float4 v = row[lane];
        acc.x += v.x; acc.y += v.y; acc.z += v.z; acc.w += v.w;
    }
    float inv = 1.0f / (float)ns;
    float4 o;
    o.x = fmaxf(acc.x * inv, 0.0f);
    o.y = fmaxf(acc.y * inv, 0.0f);
    o.z = fmaxf(acc.z * inv, 0.0f);
    o.w = fmaxf(acc.w * inv, 0.0f);
    ((float4*)(out + (size_t)warp * D_FEAT))[lane] = o;
}

// ---------------------------------------------------------------------------
// kernel_launch: graph-capturable, allocation-free.
// Inputs (metadata order): features f32[N,128], nodes i32[B], neighs i32[B,K],
// num_sample i32 scalar. Output: f32[B,128].
// ---------------------------------------------------------------------------
extern "C" void kernel_launch(void* const* d_in, const int* in_sizes, int n_in,
                              void* d_out, int out_size) {
    const float* feats = (const float*)d_in[0];
    const int* nodes = (const int*)d_in[1];
    const int* neighs = (const int*)d_in[2];
    const int* ns_ptr = (n_in > 3) ? (const int*)d_in[3] : nullptr;

    int n_nodes = in_sizes[0] / D_FEAT;
    if (n_nodes > MAX_NODES) n_nodes = MAX_NODES;
    int B = in_sizes[1];
    int K = (B > 0) ? (in_sizes[2] / B) : 0;

    // 1 warp per node, 8 warps (256 threads) per block
    int norm_blocks = (n_nodes * 32 + 255) / 256;
    norms_kernel<<<norm_blocks, 256>>>(feats, n_nodes);

    int agg_blocks = (B * 32 + 255) / 256;
    agg_kernel<<<agg_blocks, 256>>>(feats, nodes, neighs, ns_ptr,
                                    (float*)d_out, B, K);
}